// round 9
// baseline (speedup 1.0000x reference)
#include <cuda_runtime.h>
#include <math.h>

#define NQ 20
#define NSTATE (1 << NQ)

typedef unsigned long long u64;

__device__ __align__(16) float2 d_state[NSTATE];
__device__ float d_partial[512];

// ---------- packed f32x2 helpers ----------
__device__ __forceinline__ u64 pack2(float lo, float hi) {
    u64 d; asm("mov.b64 %0,{%1,%2};" : "=l"(d) : "f"(lo), "f"(hi)); return d;
}
__device__ __forceinline__ u64 swp(u64 x) {
    u64 d;
    asm("{\n\t.reg .b32 lo,hi;\n\tmov.b64 {lo,hi}, %1;\n\tmov.b64 %0,{hi,lo};\n\t}"
        : "=l"(d) : "l"(x));
    return d;
}
__device__ __forceinline__ u64 mul2(u64 a, u64 b) {
    u64 d; asm("mul.rn.f32x2 %0,%1,%2;" : "=l"(d) : "l"(a), "l"(b)); return d;
}
__device__ __forceinline__ u64 fma2(u64 a, u64 b, u64 c) {
    u64 d; asm("fma.rn.f32x2 %0,%1,%2,%3;" : "=l"(d) : "l"(a), "l"(b), "l"(c)); return d;
}
__device__ __forceinline__ float2 unp(u64 x) {
    float2 f; asm("mov.b64 {%0,%1}, %2;" : "=f"(f.x), "=f"(f.y) : "l"(x)); return f;
}
__device__ __forceinline__ float tanh_ap(float x) {
    float y; asm("tanh.approx.f32 %0,%1;" : "=f"(y) : "f"(x)); return y;
}

// gate packed layout: [axx, bxx, bxy, cxx, cxy, dxx, dxy] (stride 8 in smem)
__device__ __forceinline__ void make_gate_packed(const float* p, u64* dst) {
    float st, ct, sl, cl, sp, cp;
    sincosf(0.5f * p[0], &st, &ct);
    sincosf(p[2], &sl, &cl);
    sincosf(p[1], &sp, &cp);
    float bx = -cl * st, by = -sl * st;
    float cx = cp * st, cy = sp * st;
    float cpl = cp * cl - sp * sl, spl = sp * cl + cp * sl;
    float dx = cpl * ct, dy = spl * ct;
    dst[0] = pack2(ct, ct);
    dst[1] = pack2(bx, bx);
    dst[2] = pack2(-by, by);
    dst[3] = pack2(cx, cx);
    dst[4] = pack2(-cy, cy);
    dst[5] = pack2(dx, dx);
    dst[6] = pack2(-dy, dy);
}

// n0 = a*x0 + b*x1 (a real), n1 = c*x0 + d*x1, complex, packed re/im in u64
__device__ __forceinline__ void cpair(const u64* g, u64& x0, u64& x1) {
    u64 x0s = swp(x0), x1s = swp(x1);
    u64 n0 = mul2(g[0], x0);
    n0 = fma2(g[1], x1, n0);
    n0 = fma2(g[2], x1s, n0);
    u64 n1 = mul2(g[3], x0);
    n1 = fma2(g[4], x0s, n1);
    n1 = fma2(g[5], x1, n1);
    n1 = fma2(g[6], x1s, n1);
    x0 = n0; x1 = n1;
}

// 8-amp register window (3 bits). J in {0,1,2}.
template <int J>
__device__ __forceinline__ void u3_reg(u64* v, const u64* sgate) {
    u64 g[7];
#pragma unroll
    for (int i = 0; i < 7; i++) g[i] = sgate[i];
#pragma unroll
    for (int p = 0; p < 4; p++) {
        int x = p & ((1 << J) - 1);
        int i0 = ((p ^ x) << 1) | x;
        cpair(g, v[i0], v[i0 | (1 << J)]);
    }
}

template <int C, int T>
__device__ __forceinline__ void cu3_reg(u64* v, const u64* sgate) {
    u64 g[7];
#pragma unroll
    for (int i = 0; i < 7; i++) g[i] = sgate[i];
    constexpr int B1 = (C < T) ? C : T;
    constexpr int B2 = (C < T) ? T : C;
#pragma unroll
    for (int p = 0; p < 2; p++) {
        int x = p & ((1 << B1) - 1);
        int t1 = ((p ^ x) << 1) | x;
        int y = t1 & ((1 << B2) - 1);
        int i0 = (((t1 ^ y) << 1) | y) | (1 << C);
        cpair(g, v[i0], v[i0 | (1 << T)]);
    }
}

// Swizzle for the 2048-entry u64 tile:
//   bit4 -> pos1, bit5 -> pos2, bit6 -> pos0^pos3  (involutive bijection)
__device__ __forceinline__ int sw(int i) {
    return i ^ (((i >> 4) & 1) << 1) ^ (((i >> 5) & 1) << 2) ^ (((i >> 6) & 1) * 9);
}

// layout with window base bit B: local index = (t low B bits) | (r << B) | (t high << (B+3))
template <int B>
__device__ __forceinline__ int lidx(int t, int r) {
    int lo = t & ((1 << B) - 1);
    return lo | (r << B) | ((t >> B) << (B + 3));
}

template <int B1, int B2, bool PRESYNC>
__device__ __forceinline__ void trans(u64* v, u64* tile, int t) {
    if (PRESYNC) __syncthreads();
#pragma unroll
    for (int r = 0; r < 8; r++) tile[sw(lidx<B1>(t, r))] = v[r];
    __syncthreads();
#pragma unroll
    for (int r = 0; r < 8; r++) v[r] = tile[sw(lidx<B2>(t, r))];
}

// gate schedule tables: type (0=u3, 1=cu3) and parameter index
__device__ const unsigned char K1_type[21] = {0,0,0,1,1, 0,0,1,1, 0,0,1,1, 0,0,1,1, 0,0,1,1};
__device__ const unsigned char K1_idx[21]  = {0,1,2,0,1, 3,4,2,3, 5,6,4,5, 7,8,6,7, 9,10,8,9};
__device__ const unsigned char K2_type[19] = {0,0,1,1, 0,0,1,1, 0,0,1,1, 0,0,1,1, 0,1,1};
__device__ const unsigned char K2_idx[19]  = {11,12,10,11, 13,14,12,13, 15,16,14,15, 17,18,16,17, 19,18,19};

// ============================================================================
// K1 body: local bits = g0..g10; enters w1 (B=0: v[r] = bits 0..2), exits B=8.
// Gates: U3 q0..10, CU3 (0,1)..(9,10). 5 windows, 4 transposes.
// ============================================================================
__device__ __forceinline__ void K1_body(u64* v, u64* tile, const u64* sg, int t) {
    u3_reg<0>(v, sg + 0 * 8); u3_reg<1>(v, sg + 1 * 8); u3_reg<2>(v, sg + 2 * 8);
    cu3_reg<0, 1>(v, sg + 3 * 8); cu3_reg<1, 2>(v, sg + 4 * 8);
    trans<0, 2, false>(v, tile, t);
    u3_reg<1>(v, sg + 5 * 8); u3_reg<2>(v, sg + 6 * 8);
    cu3_reg<0, 1>(v, sg + 7 * 8); cu3_reg<1, 2>(v, sg + 8 * 8);
    trans<2, 4, true>(v, tile, t);
    u3_reg<1>(v, sg + 9 * 8); u3_reg<2>(v, sg + 10 * 8);
    cu3_reg<0, 1>(v, sg + 11 * 8); cu3_reg<1, 2>(v, sg + 12 * 8);
    trans<4, 6, true>(v, tile, t);
    u3_reg<1>(v, sg + 13 * 8); u3_reg<2>(v, sg + 14 * 8);
    cu3_reg<0, 1>(v, sg + 15 * 8); cu3_reg<1, 2>(v, sg + 16 * 8);
    trans<6, 8, true>(v, tile, t);
    u3_reg<1>(v, sg + 17 * 8); u3_reg<2>(v, sg + 18 * 8);
    cu3_reg<0, 1>(v, sg + 19 * 8); cu3_reg<1, 2>(v, sg + 20 * 8);
}

// ============================================================================
// K2 body: local l0..l9 = g10..g19, l10 = g0; enters w1 (B=0), exits B=8.
// Gates: U3 q11..19, CU3 (10,11)..(18,19),(19,0). 5 windows, 4 transposes.
// ============================================================================
template <bool PRESYNC>
__device__ __forceinline__ void K2_body(u64* v, u64* tile, const u64* sg, int t) {
    u3_reg<1>(v, sg + 0 * 8); u3_reg<2>(v, sg + 1 * 8);
    cu3_reg<0, 1>(v, sg + 2 * 8); cu3_reg<1, 2>(v, sg + 3 * 8);
    trans<0, 2, PRESYNC>(v, tile, t);
    u3_reg<1>(v, sg + 4 * 8); u3_reg<2>(v, sg + 5 * 8);
    cu3_reg<0, 1>(v, sg + 6 * 8); cu3_reg<1, 2>(v, sg + 7 * 8);
    trans<2, 4, true>(v, tile, t);
    u3_reg<1>(v, sg + 8 * 8); u3_reg<2>(v, sg + 9 * 8);
    cu3_reg<0, 1>(v, sg + 10 * 8); cu3_reg<1, 2>(v, sg + 11 * 8);
    trans<4, 6, true>(v, tile, t);
    u3_reg<1>(v, sg + 12 * 8); u3_reg<2>(v, sg + 13 * 8);
    cu3_reg<0, 1>(v, sg + 14 * 8); cu3_reg<1, 2>(v, sg + 15 * 8);
    trans<6, 8, true>(v, tile, t);
    u3_reg<1>(v, sg + 16 * 8);
    cu3_reg<0, 1>(v, sg + 17 * 8); cu3_reg<1, 2>(v, sg + 18 * 8);
}

// K2 exit-layout store: v[r] pairs with v[r|4] (differ in g0) -> 16B stores.
// g = r2 | (cta<<1) | (tid<<10) | (r0<<18) | (r1<<19)
__device__ __forceinline__ void K2_store(const u64* v, u64* ds, int tid, int cta) {
#pragma unroll
    for (int r = 0; r < 4; r++) {
        int g = (cta << 1) | (tid << 10) | ((r & 1) << 18) | (((r >> 1) & 1) << 19);
        ulonglong2 w; w.x = v[r]; w.y = v[r | 4];
        *reinterpret_cast<ulonglong2*>(ds + g) = w;
    }
}

// ============================================================================
// Fused K1(0)+K2(0): after K1(0) from |0..0>, only the 2048 amps with
// g11..g19 = 0 are nonzero. Every CTA computes that tile redundantly, extracts
// its 2 needed amps, runs K2(0).
// ============================================================================
__global__ void __launch_bounds__(256, 4) gate_AB0(const float* __restrict__ u3p,
                                                   const float* __restrict__ cu3p) {
    __shared__ u64 tile[2048];
    __shared__ u64 sg[40 * 8];
    int tid = threadIdx.x, cta = blockIdx.x;

    if (tid < 40) {
        const float* p;
        if (tid < 21) p = K1_type[tid] ? cu3p + K1_idx[tid] * 3 : u3p + K1_idx[tid] * 3;
        else {
            int s = tid - 21;
            p = K2_type[s] ? cu3p + K2_idx[s] * 3 : u3p + K2_idx[s] * 3;
        }
        make_gate_packed(p, sg + tid * 8);
    }

    u64 v[8];
#pragma unroll
    for (int r = 0; r < 8; r++) v[r] = 0ull;
    if (tid == 0) v[0] = pack2(1.f, 0.f);  // |0..0> in w1 layout
    __syncthreads();

    K1_body(v, tile, sg, tid);

    // write K1(0) tile at canonical local index (B=8 layout: l = tid | (r<<8))
#pragma unroll
    for (int r = 0; r < 8; r++) tile[sw(tid | (r << 8))] = v[r];
    __syncthreads();

    // K2 w1 nonzero inputs: K2-local l3..l9 = g13..g19 = tid bits 0..6 (must be 0),
    // l10 = g0 = tid bit 7; tile index = g0 | (g1..g9 = cta)<<1 | (g10 = r)<<10.
    u64 a0 = 0ull, a1 = 0ull;
    if ((tid & 127) == 0) {
        int b = (tid >> 7) | (cta << 1);
        a0 = tile[sw(b)];          // g10 = 0
        a1 = tile[sw(b | 1024)];   // g10 = 1
    }
#pragma unroll
    for (int r = 0; r < 8; r++) v[r] = 0ull;
    v[0] = a0; v[1] = a1;

    K2_body<true>(v, tile, sg + 21 * 8, tid);
    K2_store(v, (u64*)d_state, tid, cta);
}

// ============================================================================
// K1 (k=1,2): coalesced load (64B/thread) & store; canonical state layout.
// ============================================================================
__global__ void __launch_bounds__(256, 4) gate_K1(const float* __restrict__ u3p,
                                                  const float* __restrict__ cu3p, int k) {
    __shared__ u64 tile[2048];
    __shared__ u64 sg[21 * 8];
    int tid = threadIdx.x, cta = blockIdx.x;
    u64* gp = (u64*)d_state + ((size_t)cta << 11);

    if (tid < 21) {
        int q = k * NQ + K1_idx[tid];
        const float* p = K1_type[tid] ? cu3p + q * 3 : u3p + q * 3;
        make_gate_packed(p, sg + tid * 8);
    }

    u64 v[8];
    const ulonglong2* g2 = (const ulonglong2*)gp;
#pragma unroll
    for (int j = 0; j < 4; j++) {  // v[r] = gp[(tid<<3)|r]
        ulonglong2 w = g2[tid * 4 + j];
        v[2 * j] = w.x; v[2 * j + 1] = w.y;
    }
    __syncthreads();

    K1_body(v, tile, sg, tid);

#pragma unroll
    for (int r = 0; r < 8; r++) gp[tid | (r << 8)] = v[r];
}

// ============================================================================
// K2 (k=1,2): cta = g1..9. Load: g = (tid>>7)|(cta<<1)|(r<<10)|((tid&127)<<13).
// LAST fuses the pointwise finalize + bit-reversed output + partial sums.
// ============================================================================
template <bool LAST>
__global__ void __launch_bounds__(256, 4) gate_K2(const float* __restrict__ u3p,
                                                  const float* __restrict__ cu3p, int k,
                                                  float* __restrict__ out) {
    __shared__ u64 tile[2048];
    __shared__ u64 sg[19 * 8];
    int tid = threadIdx.x, cta = blockIdx.x;

    if (tid < 19) {
        int q = k * NQ + K2_idx[tid];
        const float* p = K2_type[tid] ? cu3p + q * 3 : u3p + q * 3;
        make_gate_packed(p, sg + tid * 8);
    }

    u64* ds = (u64*)d_state;
    int b0 = (tid >> 7) | (cta << 1) | ((tid & 127) << 13);
    u64 v[8];
#pragma unroll
    for (int r = 0; r < 8; r++) v[r] = ds[b0 | (r << 10)];
    __syncthreads();

    K2_body<false>(v, tile, sg, tid);

    if (!LAST) {
        K2_store(v, ds, tid, cta);
    } else {
        // exit layout: g = r2 | (cta<<1) | (tid<<10) | (r0<<18) | (r1<<19)
        // out_idx = brev20(g) = (r2<<19) | (rev9(cta)<<10) | (rev8(tid)<<2) | (r0<<1) | r1
        float xv[8];
        float sum = 0.f;
#pragma unroll
        for (int r = 0; r < 8; r++) {
            float2 a = unp(v[r]);
            float pr = a.x * a.x + a.y * a.y;
            float t = 0.8f * tanh_ap(52428.8f * pr);  // gamma * 2^19
            xv[r] = __powf(t, 0.3f);
            sum += xv[r];
        }
        int base = ((int)(__brev((unsigned)cta) >> 23) << 10) |
                   ((int)(__brev((unsigned)tid) >> 24) << 2);
        *(float4*)(out + base) = make_float4(xv[0], xv[2], xv[1], xv[3]);
        *(float4*)(out + (base | (1 << 19))) = make_float4(xv[4], xv[6], xv[5], xv[7]);

        for (int o = 16; o > 0; o >>= 1) sum += __shfl_down_sync(0xffffffffu, sum, o);
        __shared__ float red[8];
        if ((tid & 31) == 0) red[tid >> 5] = sum;
        __syncthreads();
        if (tid == 0) {
            float s = 0.f;
#pragma unroll
            for (int w = 0; w < 8; w++) s += red[w];
            d_partial[cta] = s;
        }
    }
}

// mean from 512 partials (redundant per CTA, L2-hot), then subtract
__global__ void __launch_bounds__(256) finalize_sub(float4* __restrict__ o4) {
    int tid = threadIdx.x;
    int i = blockIdx.x * 256 + tid;
    float4 x = o4[i];

    float s = d_partial[tid] + d_partial[tid + 256];
    for (int o = 16; o > 0; o >>= 1) s += __shfl_down_sync(0xffffffffu, s, o);
    __shared__ float red[8];
    __shared__ float mean;
    if ((tid & 31) == 0) red[tid >> 5] = s;
    __syncthreads();
    if (tid == 0) {
        float t = 0.f;
#pragma unroll
        for (int w = 0; w < 8; w++) t += red[w];
        mean = t * (1.0f / 1048576.0f);
    }
    __syncthreads();
    float m = mean;
    x.x -= m; x.y -= m; x.z -= m; x.w -= m;
    o4[i] = x;
}

extern "C" void kernel_launch(void* const* d_in, const int* in_sizes, int n_in,
                              void* d_out, int out_size) {
    const float* u3p = (const float*)d_in[0];   // (3, 20, 3)
    const float* cu3p = (const float*)d_in[1];  // (3, 20, 3)
    float* out = (float*)d_out;                 // 2^20 floats

    gate_AB0<<<512, 256>>>(u3p, cu3p);
    gate_K1<<<512, 256>>>(u3p, cu3p, 1);
    gate_K2<false><<<512, 256>>>(u3p, cu3p, 1, out);
    gate_K1<<<512, 256>>>(u3p, cu3p, 2);
    gate_K2<true><<<512, 256>>>(u3p, cu3p, 2, out);
    finalize_sub<<<1024, 256>>>((float4*)out);
}

// round 12
// speedup vs baseline: 1.1178x; 1.1178x over previous
#include <cuda_runtime.h>
#include <math.h>

typedef unsigned long long u64;

__device__ __align__(16) float2 d_state[1 << 20];
__device__ float d_partial[256];

// ---------- packed f32x2 helpers ----------
__device__ __forceinline__ u64 pack2(float lo, float hi) {
    u64 d; asm("mov.b64 %0,{%1,%2};" : "=l"(d) : "f"(lo), "f"(hi)); return d;
}
__device__ __forceinline__ u64 swp(u64 x) {
    u64 d;
    asm("{\n\t.reg .b32 lo,hi;\n\tmov.b64 {lo,hi}, %1;\n\tmov.b64 %0,{hi,lo};\n\t}"
        : "=l"(d) : "l"(x));
    return d;
}
__device__ __forceinline__ u64 mul2(u64 a, u64 b) {
    u64 d; asm("mul.rn.f32x2 %0,%1,%2;" : "=l"(d) : "l"(a), "l"(b)); return d;
}
__device__ __forceinline__ u64 fma2(u64 a, u64 b, u64 c) {
    u64 d; asm("fma.rn.f32x2 %0,%1,%2,%3;" : "=l"(d) : "l"(a), "l"(b), "l"(c)); return d;
}
__device__ __forceinline__ float2 unp(u64 x) {
    float2 f; asm("mov.b64 {%0,%1}, %2;" : "=f"(f.x), "=f"(f.y) : "l"(x)); return f;
}
__device__ __forceinline__ float tanh_ap(float x) {
    float y; asm("tanh.approx.f32 %0,%1;" : "=f"(y) : "f"(x)); return y;
}
__device__ __forceinline__ u64 shfl64(u64 x, int m) {
    unsigned lo = (unsigned)x, hi = (unsigned)(x >> 32);
    lo = __shfl_xor_sync(0xffffffffu, lo, m);
    hi = __shfl_xor_sync(0xffffffffu, hi, m);
    return (u64)lo | ((u64)hi << 32);
}

// ---------- gate preparation ----------
struct C2 { float x, y; };
__device__ __forceinline__ void u3vals(const float* p, C2& a, C2& b, C2& c, C2& d) {
    float st, ct, sl, cl, sp, cp;
    sincosf(0.5f * p[0], &st, &ct);
    sincosf(p[2], &sl, &cl);
    sincosf(p[1], &sp, &cp);
    a = {ct, 0.f};
    b = {-cl * st, -sl * st};
    c = {cp * st, sp * st};
    d = {(cp * cl - sp * sl) * ct, (sp * cl + cp * sl) * ct};
}
__device__ __forceinline__ C2 cmul(C2 u, C2 v) { return {u.x * v.x - u.y * v.y, u.x * v.y + u.y * v.x}; }
__device__ __forceinline__ C2 cadd(C2 u, C2 v) { return {u.x + v.x, u.y + v.y}; }

// 8-u64 general 2x2 gate: rows (a,b),(c,d); each complex coef as ([gx,gx],[-gy,gy])
__device__ __forceinline__ void pack8(u64* dst, C2 a, C2 b, C2 c, C2 d) {
    dst[0] = pack2(a.x, a.x); dst[1] = pack2(-a.y, a.y);
    dst[2] = pack2(b.x, b.x); dst[3] = pack2(-b.y, b.y);
    dst[4] = pack2(c.x, c.x); dst[5] = pack2(-c.y, c.y);
    dst[6] = pack2(d.x, d.x); dst[7] = pack2(-d.y, d.y);
}
__device__ __forceinline__ void prep_u3(u64* slot, const float* p) {
    C2 a, b, c, d; u3vals(p, a, b, c, d); pack8(slot, a, b, c, d);
}
// MC(ctrl q, tgt q+1): M0 = U3(tgt params) at +0;  M1 = u3(cu3 params) @ M0 at +8
__device__ __forceinline__ void prep_mc(u64* slot, const float* pu3_tgt, const float* pcu3) {
    C2 a0, b0, c0, d0, ua, ub, uc, ud;
    u3vals(pu3_tgt, a0, b0, c0, d0);
    u3vals(pcu3, ua, ub, uc, ud);
    pack8(slot, a0, b0, c0, d0);
    pack8(slot + 8,
          cadd(cmul(ua, a0), cmul(ub, c0)), cadd(cmul(ua, b0), cmul(ub, d0)),
          cadd(cmul(uc, a0), cmul(ud, c0)), cadd(cmul(uc, b0), cmul(ud, d0)));
}

// n0 = a*x0 + b*x1, n1 = c*x0 + d*x1 (all complex), packed re/im u64
__device__ __forceinline__ void cpair8(const u64* g, u64& x0, u64& x1) {
    u64 x0s = swp(x0), x1s = swp(x1);
    u64 n0 = fma2(g[0], x0, fma2(g[1], x0s, fma2(g[2], x1, mul2(g[3], x1s))));
    u64 n1 = fma2(g[4], x0, fma2(g[5], x0s, fma2(g[6], x1, mul2(g[7], x1s))));
    x0 = n0; x1 = n1;
}

// ---------- register-space gate ops on 16 amps (4 reg bits) ----------
template <int T>
__device__ __forceinline__ void g_reg(u64* v, const u64* slot) {
    u64 g[8];
#pragma unroll
    for (int i = 0; i < 8; i++) g[i] = slot[i];
#pragma unroll
    for (int p = 0; p < 8; p++) {
        int x = p & ((1 << T) - 1);
        int i0 = ((p ^ x) << 1) | x;
        cpair8(g, v[i0], v[i0 | (1 << T)]);
    }
}

// bit-controlled select gate, ctrl reg bit C, tgt reg bit T
template <int C, int T>
__device__ __forceinline__ void mc_reg(u64* v, const u64* slot) {
#pragma unroll
    for (int cb = 0; cb < 2; cb++) {
        u64 g[8];
#pragma unroll
        for (int i = 0; i < 8; i++) g[i] = slot[cb * 8 + i];
#pragma unroll
        for (int p = 0; p < 8; p++) {
            int x = p & ((1 << T) - 1);
            int i0 = ((p ^ x) << 1) | x;
            if (((i0 >> C) & 1) == cb) cpair8(g, v[i0], v[i0 | (1 << T)]);
        }
    }
}

// plain CU3: apply gate only where ctrl reg bit C = 1
template <int C, int T>
__device__ __forceinline__ void cu3_reg(u64* v, const u64* slot) {
    u64 g[8];
#pragma unroll
    for (int i = 0; i < 8; i++) g[i] = slot[i];
#pragma unroll
    for (int p = 0; p < 8; p++) {
        int x = p & ((1 << T) - 1);
        int i0 = ((p ^ x) << 1) | x;
        if ((i0 >> C) & 1) cpair8(g, v[i0], v[i0 | (1 << T)]);
    }
}

// ---------- lane-space (shuffle) gate ops ----------
// self amp has target bit = hi; update: v = P*v + Q*p, P = hi? d : a, Q = hi? c : b.
// MC with ctrl reg bit3, target lane bit0:
__device__ __forceinline__ void mc_mixed(u64* v, const u64* slot, int lane) {
    bool hi = lane & 1;
#pragma unroll
    for (int cb = 0; cb < 2; cb++) {
        const u64* g = slot + cb * 8;
        u64 Px = hi ? g[6] : g[0], Pxy = hi ? g[7] : g[1];
        u64 Qx = hi ? g[4] : g[2], Qxy = hi ? g[5] : g[3];
#pragma unroll
        for (int r = cb * 8; r < cb * 8 + 8; r++) {
            u64 p = shfl64(v[r], 1);
            v[r] = fma2(Px, v[r], fma2(Pxy, swp(v[r]), fma2(Qx, p, mul2(Qxy, swp(p)))));
        }
    }
}

// MC with ctrl lane mask cmask, target lane mask tmask
__device__ __forceinline__ void mc_lane(u64* v, const u64* slot, int lane, int cmask, int tmask) {
    const u64* g = (lane & cmask) ? slot + 8 : slot;
    bool hi = lane & tmask;
    u64 Px = hi ? g[6] : g[0], Pxy = hi ? g[7] : g[1];
    u64 Qx = hi ? g[4] : g[2], Qxy = hi ? g[5] : g[3];
#pragma unroll
    for (int r = 0; r < 16; r++) {
        u64 p = shfl64(v[r], tmask);
        v[r] = fma2(Px, v[r], fma2(Pxy, swp(v[r]), fma2(Qx, p, mul2(Qxy, swp(p)))));
    }
}

// smem swizzle for 4096-u64 tile: fold bits 4..7 and 8..11 into 0..3
__device__ __forceinline__ int s(int i) { return i ^ (((i >> 4) ^ (i >> 8)) & 15); }

// ============================================================================
// K1 body. P1: reg=q0..3, lane=q4..8, warp=q9..11. P2: reg=q8..11, lane=q3..7, warp=q0..2.
// Gates: U3(0); MC(0,1)..(10,11). sg = 12 slots x 16 u64. One transpose.
// ============================================================================
__device__ __forceinline__ void K1_body(u64* v, u64* tile, const u64* sg, int w, int lane) {
    g_reg<0>(v, sg);                       // U3 q0
    mc_reg<0, 1>(v, sg + 16);              // MC(0,1)
    mc_reg<1, 2>(v, sg + 32);
    mc_reg<2, 3>(v, sg + 48);
    mc_mixed(v, sg + 64, lane);            // MC(3,4): ctrl reg3, tgt lane0
    mc_lane(v, sg + 80, lane, 1, 2);       // MC(4,5)
    mc_lane(v, sg + 96, lane, 2, 4);       // MC(5,6)
    mc_lane(v, sg + 112, lane, 4, 8);      // MC(6,7)
    mc_lane(v, sg + 128, lane, 8, 16);     // MC(7,8)
    // transpose P1 -> P2 (canonical local idx = q0..11)
#pragma unroll
    for (int r = 0; r < 16; r++) tile[s(r | (lane << 4) | (w << 9))] = v[r];
    __syncthreads();
#pragma unroll
    for (int r = 0; r < 16; r++) v[r] = tile[s(w | (lane << 3) | (r << 8))];
    mc_reg<0, 1>(v, sg + 144);             // MC(8,9)
    mc_reg<1, 2>(v, sg + 160);             // MC(9,10)
    mc_reg<2, 3>(v, sg + 176);             // MC(10,11)
}

// ============================================================================
// K2 body. Local l0..2=q0..2, l3..11=q11..19; cta=q3..10.
// P1: reg=l3..6, lane=l7..11, warp=l0..2. P2: reg={l0,l1,l2,l11}, lane=l3..7, warp=l8..10.
// Gates: MC(11,12)..(18,19); CU3(19,0). sg = 9 slots x 16 u64. One transpose.
// ============================================================================
template <bool PRESYNC>
__device__ __forceinline__ void K2_body(u64* v, u64* tile, const u64* sg, int w, int lane) {
    mc_reg<0, 1>(v, sg);                   // MC(11,12)
    mc_reg<1, 2>(v, sg + 16);
    mc_reg<2, 3>(v, sg + 32);
    mc_mixed(v, sg + 48, lane);            // MC(14,15): ctrl reg3, tgt lane0
    mc_lane(v, sg + 64, lane, 1, 2);       // MC(15,16)
    mc_lane(v, sg + 80, lane, 2, 4);       // MC(16,17)
    mc_lane(v, sg + 96, lane, 4, 8);       // MC(17,18)
    mc_lane(v, sg + 112, lane, 8, 16);     // MC(18,19)
    if (PRESYNC) __syncthreads();
#pragma unroll
    for (int r = 0; r < 16; r++) tile[s(w | (r << 3) | (lane << 7))] = v[r];
    __syncthreads();
#pragma unroll
    for (int r = 0; r < 16; r++)
        v[r] = tile[s((r & 7) | (lane << 3) | (w << 8) | ((r >> 3) << 11))];
    cu3_reg<3, 0>(v, sg + 128);            // CU3(19,0): ctrl l11=reg3, tgt l0=reg0
}

// gate prep (one thread per slot)
__device__ __forceinline__ void prep_K1(u64* sg, const float* u3p, const float* cu3p,
                                        int k, int tid) {
    if (tid == 0) prep_u3(sg, u3p + k * 60);
    else if (tid <= 11)
        prep_mc(sg + tid * 16, u3p + (k * 20 + tid) * 3, cu3p + (k * 20 + tid - 1) * 3);
}
__device__ __forceinline__ void prep_K2(u64* sg, const float* u3p, const float* cu3p,
                                        int k, int t) {
    if (t < 8) prep_mc(sg + t * 16, u3p + (k * 20 + 12 + t) * 3, cu3p + (k * 20 + 11 + t) * 3);
    else if (t == 8) prep_u3(sg + 128, cu3p + (k * 20 + 19) * 3);
}

// π  (K1-exit / K2-entry): addr = q11 | q3..7<<1 | q8..10<<6 | q0..2<<9 | q12..19<<12
// π' (K2-exit / K1-entry): addr = q0..2 | q11..15<<3 | q19<<8 | q16..18<<9 | q3..10<<12

// K2 exit store in π': thread P2 (w=l8..10=q16..18, lane=l3..7=q11..15), regs j|h<<3
__device__ __forceinline__ void K2_store(const u64* v, u64* ds, int w, int lane, int cta) {
#pragma unroll
    for (int h = 0; h < 2; h++) {
        int a = (lane << 3) | (h << 8) | (w << 9) | (cta << 12);
        ulonglong2* m = (ulonglong2*)(ds + a);
#pragma unroll
        for (int t = 0; t < 4; t++) {
            ulonglong2 x; x.x = v[h * 8 + 2 * t]; x.y = v[h * 8 + 2 * t + 1];
            m[t] = x;
        }
    }
}

// ============================================================================
// Fused K1(0)+K2(0): after K1(0) from |0..0>, nonzero amps have q12..19 = 0.
// Every CTA computes that 4096-amp tile redundantly, extracts its inputs
// (BOTH q11=0 and q11=1 amps — q11 is free!), runs K2(0).
// ============================================================================
__global__ void __launch_bounds__(256, 2) gate_AB0(const float* __restrict__ u3p,
                                                   const float* __restrict__ cu3p) {
    __shared__ u64 tile[4096];
    __shared__ u64 sg1[192];
    __shared__ u64 sg2[144];
    int tid = threadIdx.x, cta = blockIdx.x;
    int w = tid >> 5, lane = tid & 31;

    prep_K1(sg1, u3p, cu3p, 0, tid);
    if (tid >= 12 && tid <= 20) prep_K2(sg2, u3p, cu3p, 0, tid - 12);

    u64 v[16];
#pragma unroll
    for (int r = 0; r < 16; r++) v[r] = 0ull;
    if (tid == 0) v[0] = pack2(1.f, 0.f);
    __syncthreads();

    K1_body(v, tile, sg1, w, lane);

    __syncthreads();  // WAR: transpose readers done before publish
#pragma unroll
    for (int r = 0; r < 16; r++) tile[s(w | (lane << 3) | (r << 8))] = v[r];
    __syncthreads();

    // K2-P1 nonzero inputs need q12..14 = 0 (reg bits 1..3) and q15..19 = 0 (lane),
    // but q11 (reg bit 0) is free: fetch BOTH v[0] (q11=0) and v[1] (q11=1).
    // tile idx = q0..2=w | q3..10=cta<<3 | q11<<11.
    u64 a0 = 0ull, a1 = 0ull;
    if (lane == 0) {
        int b = w | (cta << 3);
        a0 = tile[s(b)];            // q11 = 0
        a1 = tile[s(b | 2048)];     // q11 = 1
    }
#pragma unroll
    for (int r = 0; r < 16; r++) v[r] = 0ull;
    v[0] = a0; v[1] = a1;

    K2_body<true>(v, tile, sg2, w, lane);
    K2_store(v, (u64*)d_state, w, lane, cta);
}

// ============================================================================
// K1 (k=1,2): load π', gates, store π.
// ============================================================================
__global__ void __launch_bounds__(256, 2) gate_K1(const float* __restrict__ u3p,
                                                  const float* __restrict__ cu3p, int k) {
    __shared__ u64 tile[4096];
    __shared__ u64 sg[192];
    int tid = threadIdx.x, cta = blockIdx.x;
    int w = tid >> 5, lane = tid & 31;

    prep_K1(sg, u3p, cu3p, k, tid);

    // load π': thread P1 (reg: j=q0..2, h=q3; lane=q4..8; w: q9..10=w&3, q11=w>>2)
    u64 v[16];
    const u64* ds = (const u64*)d_state;
    int cb = ((cta & 15) << 4) | ((cta >> 7) << 8) | (((cta >> 4) & 7) << 9);
#pragma unroll
    for (int h = 0; h < 2; h++) {
        int a = cb | ((w >> 2) << 3) | (h << 12) | (lane << 13) | ((w & 3) << 18);
        const ulonglong2* m = (const ulonglong2*)(ds + a);
#pragma unroll
        for (int t = 0; t < 4; t++) {
            ulonglong2 x = m[t];
            v[h * 8 + 2 * t] = x.x; v[h * 8 + 2 * t + 1] = x.y;
        }
    }
    __syncthreads();  // gate prep ready

    K1_body(v, tile, sg, w, lane);

    // store π: thread P2 (w=q0..2, lane=q3..7, r=q8..11); pair dim = q11 (r bit 3)
    u64* dw = (u64*)d_state;
#pragma unroll
    for (int rr = 0; rr < 8; rr++) {
        int a = (lane << 1) | (rr << 6) | (w << 9) | (cta << 12);
        ulonglong2 x; x.x = v[rr]; x.y = v[rr | 8];
        *(ulonglong2*)(dw + a) = x;
    }
}

// ============================================================================
// K2 (k=1,2): load π, gates; store π' or fused finalize.
// ============================================================================
template <bool LAST>
__global__ void __launch_bounds__(256, 2) gate_K2(const float* __restrict__ u3p,
                                                  const float* __restrict__ cu3p, int k,
                                                  float* __restrict__ out) {
    __shared__ u64 tile[4096];
    __shared__ u64 sg[144];
    int tid = threadIdx.x, cta = blockIdx.x;
    int w = tid >> 5, lane = tid & 31;

    if (tid < 9) prep_K2(sg, u3p, cu3p, k, tid);

    // load π: thread P1 (w=q0..2, lane=q15..19, rr=q12..14, pair=q11, cta=q3..10)
    u64 v[16];
    const u64* ds = (const u64*)d_state;
    int cb = ((cta & 31) << 1) | (((cta >> 5) & 7) << 6);
#pragma unroll
    for (int rr = 0; rr < 8; rr++) {
        int a = cb | (w << 9) | (rr << 12) | (lane << 15);
        ulonglong2 x = *(const ulonglong2*)(ds + a);
        v[2 * rr] = x.x; v[2 * rr + 1] = x.y;
    }
    __syncthreads();

    K2_body<false>(v, tile, sg, w, lane);

    if (!LAST) {
        K2_store(v, (u64*)d_state, w, lane, cta);
    } else {
        // P2 thread: w=q16..18, lane=q11..15, cta=q3..10, reg: j=q0..2, h=q19
        // out = brev20(g) = h | rev3(w)<<1 | rev5(lane)<<4 | rev8(cta)<<9 | rev3(j)<<17
        float xv[16];
        float sum = 0.f;
#pragma unroll
        for (int r = 0; r < 16; r++) {
            float2 a = unp(v[r]);
            float pr = a.x * a.x + a.y * a.y;
            float t = 0.8f * tanh_ap(52428.8f * pr);  // gamma * 2^19
            xv[r] = __powf(t, 0.3f);
            sum += xv[r];
        }
        int base = ((int)(__brev((unsigned)w) >> 29) << 1) |
                   ((int)(__brev((unsigned)lane) >> 27) << 4) |
                   ((int)(__brev((unsigned)cta) >> 24) << 9);
#pragma unroll
        for (int j = 0; j < 8; j++) {
            int rj = (int)(__brev((unsigned)j) >> 29);
            float2 o; o.x = xv[j]; o.y = xv[j | 8];  // h = 0, 1
            *(float2*)(out + (base | (rj << 17))) = o;
        }
        for (int o = 16; o > 0; o >>= 1) sum += __shfl_down_sync(0xffffffffu, sum, o);
        __shared__ float red[8];
        if (lane == 0) red[w] = sum;
        __syncthreads();
        if (tid == 0) {
            float t = 0.f;
#pragma unroll
            for (int i = 0; i < 8; i++) t += red[i];
            d_partial[cta] = t;
        }
    }
}

// mean from 256 partials (redundant per CTA, L2-hot), then subtract
__global__ void __launch_bounds__(256) finalize_sub(float4* __restrict__ o4) {
    int tid = threadIdx.x;
    int i = blockIdx.x * 256 + tid;
    float4 x = o4[i];

    float sv = d_partial[tid];
    for (int o = 16; o > 0; o >>= 1) sv += __shfl_down_sync(0xffffffffu, sv, o);
    __shared__ float red[8];
    __shared__ float mean;
    if ((tid & 31) == 0) red[tid >> 5] = sv;
    __syncthreads();
    if (tid == 0) {
        float t = 0.f;
#pragma unroll
        for (int wi = 0; wi < 8; wi++) t += red[wi];
        mean = t * (1.0f / 1048576.0f);
    }
    __syncthreads();
    float m = mean;
    x.x -= m; x.y -= m; x.z -= m; x.w -= m;
    o4[i] = x;
}

extern "C" void kernel_launch(void* const* d_in, const int* in_sizes, int n_in,
                              void* d_out, int out_size) {
    const float* u3p = (const float*)d_in[0];   // (3, 20, 3)
    const float* cu3p = (const float*)d_in[1];  // (3, 20, 3)
    float* out = (float*)d_out;                 // 2^20 floats

    gate_AB0<<<256, 256>>>(u3p, cu3p);
    gate_K1<<<256, 256>>>(u3p, cu3p, 1);
    gate_K2<false><<<256, 256>>>(u3p, cu3p, 1, out);
    gate_K1<<<256, 256>>>(u3p, cu3p, 2);
    gate_K2<true><<<256, 256>>>(u3p, cu3p, 2, out);
    finalize_sub<<<1024, 256>>>((float4*)out);
}

// round 13
// speedup vs baseline: 1.2359x; 1.1057x over previous
#include <cuda_runtime.h>
#include <math.h>

#define NQ 20
#define NSTATE (1 << NQ)

typedef unsigned long long u64;

__device__ __align__(16) float2 d_state[NSTATE];
__device__ float d_partial[256];

// ---------- packed f32x2 helpers ----------
__device__ __forceinline__ u64 pack2(float lo, float hi) {
    u64 d; asm("mov.b64 %0,{%1,%2};" : "=l"(d) : "f"(lo), "f"(hi)); return d;
}
__device__ __forceinline__ u64 swp(u64 x) {
    u64 d;
    asm("{\n\t.reg .b32 lo,hi;\n\tmov.b64 {lo,hi}, %1;\n\tmov.b64 %0,{hi,lo};\n\t}"
        : "=l"(d) : "l"(x));
    return d;
}
__device__ __forceinline__ u64 mul2(u64 a, u64 b) {
    u64 d; asm("mul.rn.f32x2 %0,%1,%2;" : "=l"(d) : "l"(a), "l"(b)); return d;
}
__device__ __forceinline__ u64 fma2(u64 a, u64 b, u64 c) {
    u64 d; asm("fma.rn.f32x2 %0,%1,%2,%3;" : "=l"(d) : "l"(a), "l"(b), "l"(c)); return d;
}
__device__ __forceinline__ float2 unp(u64 x) {
    float2 f; asm("mov.b64 {%0,%1}, %2;" : "=f"(f.x), "=f"(f.y) : "l"(x)); return f;
}
__device__ __forceinline__ float tanh_ap(float x) {
    float y; asm("tanh.approx.f32 %0,%1;" : "=f"(y) : "f"(x)); return y;
}

// ---------- gate construction ----------
struct C2 { float x, y; };
__device__ __forceinline__ void u3vals(const float* p, C2& a, C2& b, C2& c, C2& d) {
    float st, ct, sl, cl, sp, cp;
    sincosf(0.5f * p[0], &st, &ct);
    sincosf(p[2], &sl, &cl);
    sincosf(p[1], &sp, &cp);
    a = {ct, 0.f};
    b = {-cl * st, -sl * st};
    c = {cp * st, sp * st};
    d = {(cp * cl - sp * sl) * ct, (sp * cl + cp * sl) * ct};
}
__device__ __forceinline__ C2 cmul(C2 u, C2 v) { return {u.x * v.x - u.y * v.y, u.x * v.y + u.y * v.x}; }
__device__ __forceinline__ C2 cadd(C2 u, C2 v) { return {u.x + v.x, u.y + v.y}; }

// 8-u64 gate slot: rows (a,b),(c,d); coef z stored as [ (zx,zx), (-zy,zy) ]
__device__ __forceinline__ void pack8(u64* dst, C2 a, C2 b, C2 c, C2 d) {
    dst[0] = pack2(a.x, a.x); dst[1] = pack2(-a.y, a.y);
    dst[2] = pack2(b.x, b.x); dst[3] = pack2(-b.y, b.y);
    dst[4] = pack2(c.x, c.x); dst[5] = pack2(-c.y, c.y);
    dst[6] = pack2(d.x, d.x); dst[7] = pack2(-d.y, d.y);
}
__device__ __forceinline__ void prep_u3(u64* slot, const float* p) {
    C2 a, b, c, d; u3vals(p, a, b, c, d); pack8(slot, a, b, c, d);
}
// MC(q,q+1) slot (16 u64): M0 = U3(tgt params) at +0; M1 = u3(cu3 params) @ M0 at +8
__device__ __forceinline__ void prep_mc(u64* slot, const float* pu3_tgt, const float* pcu3) {
    C2 a0, b0, c0, d0, ua, ub, uc, ud;
    u3vals(pu3_tgt, a0, b0, c0, d0);
    u3vals(pcu3, ua, ub, uc, ud);
    pack8(slot, a0, b0, c0, d0);
    pack8(slot + 8,
          cadd(cmul(ua, a0), cmul(ub, c0)), cadd(cmul(ua, b0), cmul(ub, d0)),
          cadd(cmul(uc, a0), cmul(ud, c0)), cadd(cmul(uc, b0), cmul(ud, d0)));
}

// n0 = a*x0 + b*x1, n1 = c*x0 + d*x1. AREAL: a.y == 0 (skip g[1] term) -> 7 ops.
template <bool AREAL>
__device__ __forceinline__ void cpair(const u64* g, u64& x0, u64& x1) {
    u64 x0s = swp(x0), x1s = swp(x1);
    u64 n0 = fma2(g[2], x1, mul2(g[3], x1s));
    if (!AREAL) n0 = fma2(g[1], x0s, n0);
    n0 = fma2(g[0], x0, n0);
    u64 n1 = fma2(g[4], x0, fma2(g[5], x0s, fma2(g[6], x1, mul2(g[7], x1s))));
    x0 = n0; x1 = n1;
}

// ---------- register-window gate ops (16 amps, 4 reg bits) ----------
// U3 on reg bit T (8 pairs, real a)
template <int T>
__device__ __forceinline__ void u3_reg(u64* v, const u64* slot) {
    u64 g[8];
#pragma unroll
    for (int i = 0; i < 8; i++) g[i] = slot[i];
#pragma unroll
    for (int p = 0; p < 8; p++) {
        int x = p & ((1 << T) - 1);
        int i0 = ((p ^ x) << 1) | x;
        cpair<true>(g, v[i0], v[i0 | (1 << T)]);
    }
}

// fused select gate MC: ctrl reg bit C (C < T), M0 where ctrl=0 (real a), M1 where ctrl=1
template <int C, int T>
__device__ __forceinline__ void mc_reg(u64* v, const u64* slot) {
    {
        u64 g[8];
#pragma unroll
        for (int i = 0; i < 8; i++) g[i] = slot[i];
#pragma unroll
        for (int p = 0; p < 8; p++) {
            int x = p & ((1 << T) - 1);
            int i0 = ((p ^ x) << 1) | x;
            if (((i0 >> C) & 1) == 0) cpair<true>(g, v[i0], v[i0 | (1 << T)]);
        }
    }
    {
        u64 g[8];
#pragma unroll
        for (int i = 0; i < 8; i++) g[i] = slot[8 + i];
#pragma unroll
        for (int p = 0; p < 8; p++) {
            int x = p & ((1 << T) - 1);
            int i0 = ((p ^ x) << 1) | x;
            if (((i0 >> C) & 1) == 1) cpair<false>(g, v[i0], v[i0 | (1 << T)]);
        }
    }
}

// plain CU3 (real-a u3 applied where ctrl reg bit C = 1): 4 pairs
template <int C, int T>
__device__ __forceinline__ void cu3_reg(u64* v, const u64* slot) {
    u64 g[8];
#pragma unroll
    for (int i = 0; i < 8; i++) g[i] = slot[i];
    constexpr int B1 = (C < T) ? C : T;
    constexpr int B2 = (C < T) ? T : C;
#pragma unroll
    for (int p = 0; p < 4; p++) {
        int x = p & ((1 << B1) - 1);
        int t1 = ((p ^ x) << 1) | x;
        int y = t1 & ((1 << B2) - 1);
        int i0 = (((t1 ^ y) << 1) | y) | (1 << C);
        cpair<true>(g, v[i0], v[i0 | (1 << T)]);
    }
}

// bank-conflict-avoiding swizzle for the 4096-entry u64 tile (R4, proven)
__device__ __forceinline__ int sw(int i) { return i ^ ((i >> 4) & 15); }

// ============================================================================
// A body (K1 gates, fused): enters w1 (v[r]: q0..3 = r, q4..11 = tid),
// exits w4 (v[r]: q8..11 = r, q0..7 = tid). Slots: 0=U3(0), i=1..11: MC(i-1,i).
// ============================================================================
__device__ __forceinline__ void A_body(u64* v, u64* tile, const u64* sg, int tid) {
    // window {q0..3}
    u3_reg<0>(v, sg);                  // U3 q0
    mc_reg<0, 1>(v, sg + 16);          // MC(0,1)
    mc_reg<1, 2>(v, sg + 32);          // MC(1,2)
    mc_reg<2, 3>(v, sg + 48);          // MC(2,3)

    // T2 -> window {q3..6}
#pragma unroll
    for (int r = 0; r < 16; r++) tile[sw((tid << 4) | r)] = v[r];
    __syncthreads();
#pragma unroll
    for (int r = 0; r < 16; r++) v[r] = tile[sw((tid & 7) | (r << 3) | ((tid >> 3) << 7))];
    mc_reg<0, 1>(v, sg + 64);          // MC(3,4)
    mc_reg<1, 2>(v, sg + 80);          // MC(4,5)
    mc_reg<2, 3>(v, sg + 96);          // MC(5,6)

    // T3 -> window {q6..9}
    __syncthreads();
#pragma unroll
    for (int r = 0; r < 16; r++) tile[sw((tid & 7) | (r << 3) | ((tid >> 3) << 7))] = v[r];
    __syncthreads();
#pragma unroll
    for (int r = 0; r < 16; r++) v[r] = tile[sw((tid & 63) | (r << 6) | ((tid >> 6) << 10))];
    mc_reg<0, 1>(v, sg + 112);         // MC(6,7)
    mc_reg<1, 2>(v, sg + 128);         // MC(7,8)
    mc_reg<2, 3>(v, sg + 144);         // MC(8,9)

    // T4 -> window {q8..11}
    __syncthreads();
#pragma unroll
    for (int r = 0; r < 16; r++) tile[sw((tid & 63) | (r << 6) | ((tid >> 6) << 10))] = v[r];
    __syncthreads();
#pragma unroll
    for (int r = 0; r < 16; r++) v[r] = tile[sw(tid | (r << 8))];
    mc_reg<1, 2>(v, sg + 160);         // MC(9,10)
    mc_reg<2, 3>(v, sg + 176);         // MC(10,11)
}

// ============================================================================
// B body (K2 gates, fused): local l0..2 = q0..2, l3..11 = q11..19; cta = q3..10.
// Enters w1 (v[r]: l3..6 = r, l0..2 = tid&7, l7..11 = tid>>3);
// exits w3 (v[r]: l9..11 = r&7, l0 = r>>3, l1..8 = tid).
// Slots: i=0..7: MC(11+i,12+i); 8: CU3(19,0).
// ============================================================================
template <bool PRESYNC>
__device__ __forceinline__ void B_body(u64* v, u64* tile, const u64* sg, int tid) {
    // window {l3..6}
    mc_reg<0, 1>(v, sg);               // MC(11,12)
    mc_reg<1, 2>(v, sg + 16);          // MC(12,13)
    mc_reg<2, 3>(v, sg + 32);          // MC(13,14)

    // T2 -> window {l6..9}
    if (PRESYNC) __syncthreads();
#pragma unroll
    for (int r = 0; r < 16; r++) tile[sw((tid & 7) | (r << 3) | ((tid >> 3) << 7))] = v[r];
    __syncthreads();
#pragma unroll
    for (int r = 0; r < 16; r++) v[r] = tile[sw((tid & 63) | (r << 6) | ((tid >> 6) << 10))];
    mc_reg<0, 1>(v, sg + 48);          // MC(14,15)
    mc_reg<1, 2>(v, sg + 64);          // MC(15,16)
    mc_reg<2, 3>(v, sg + 80);          // MC(16,17)

    // T3 -> window {l9,l10,l11,l0}
    __syncthreads();
#pragma unroll
    for (int r = 0; r < 16; r++) tile[sw((tid & 63) | (r << 6) | ((tid >> 6) << 10))] = v[r];
    __syncthreads();
#pragma unroll
    for (int r = 0; r < 16; r++) v[r] = tile[sw((r >> 3) | (tid << 1) | ((r & 7) << 9))];
    mc_reg<0, 1>(v, sg + 96);          // MC(17,18): ctrl l9=reg0, tgt l10=reg1
    mc_reg<1, 2>(v, sg + 112);         // MC(18,19)
    cu3_reg<2, 3>(v, sg + 128);        // CU3(19,0): ctrl l11=reg2, tgt l0=reg3
}

// B final store: v[r]/v[r|8] adjacent in memory (q0 pair) -> 16B stores (R4, proven)
__device__ __forceinline__ void B_store(const u64* v, u64* ds, int tid, int cta) {
#pragma unroll
    for (int r = 0; r < 8; r++) {
        int g = ((tid & 3) << 1) | (cta << 3) | (((tid >> 2) | (r << 6)) << 11);
        ulonglong2 val; val.x = v[r]; val.y = v[r | 8];
        *reinterpret_cast<ulonglong2*>(ds + g) = val;
    }
}

// gate prep (one thread per slot)
__device__ __forceinline__ void prep_A(u64* sg, const float* u3p, const float* cu3p,
                                       int k, int tid) {
    if (tid == 0) prep_u3(sg, u3p + k * 60);
    else if (tid <= 11)
        prep_mc(sg + tid * 16, u3p + (k * NQ + tid) * 3, cu3p + (k * NQ + tid - 1) * 3);
}
__device__ __forceinline__ void prep_B(u64* sg, const float* u3p, const float* cu3p,
                                       int k, int t) {
    if (t < 8) prep_mc(sg + t * 16, u3p + (k * NQ + 12 + t) * 3, cu3p + (k * NQ + 11 + t) * 3);
    else if (t == 8) prep_u3(sg + 128, cu3p + (k * NQ + 19) * 3);
}

// ============================================================================
// Fused A(0)+B(0): after A(0) from |0..0>, only amps with q12..19 = 0 are
// nonzero. Every CTA computes that 4096-amp tile redundantly, extracts its
// 2 needed amps (q11 free!), runs B(0). (R4 structure, proven.)
// ============================================================================
__global__ void __launch_bounds__(256) gate_AB0(const float* __restrict__ u3p,
                                                const float* __restrict__ cu3p) {
    __shared__ u64 tile[4096];
    __shared__ u64 sgA[192];
    __shared__ u64 sgB[144];
    int tid = threadIdx.x, cta = blockIdx.x;

    prep_A(sgA, u3p, cu3p, 0, tid);
    if (tid >= 16 && tid <= 24) prep_B(sgB, u3p, cu3p, 0, tid - 16);

    u64 v[16];
#pragma unroll
    for (int r = 0; r < 16; r++) v[r] = 0ull;
    if (tid == 0) v[0] = pack2(1.f, 0.f);  // |0..0> in w1 layout
    __syncthreads();

    A_body(v, tile, sgA, tid);

    // publish A tile (w4 layout -> canonical local index q0..11)
    __syncthreads();
#pragma unroll
    for (int r = 0; r < 16; r++) tile[sw((r << 8) | tid)] = v[r];
    __syncthreads();

    // B w1 nonzero inputs: q0..2 = tid (tid<8), q3..10 = cta, q11 = r bit0
    u64 a0 = 0ull, a1 = 0ull;
    if (tid < 8) {
        int i0 = tid | (cta << 3);
        a0 = tile[sw(i0)];
        a1 = tile[sw(i0 | 2048)];
    }
#pragma unroll
    for (int r = 0; r < 16; r++) v[r] = 0ull;
    v[0] = a0; v[1] = a1;

    B_body<true>(v, tile, sgB, tid);
    B_store(v, (u64*)d_state, tid, cta);
}

// ============================================================================
// Kernel A (k=1,2): direct w1 load (128B contiguous per thread), w4 store.
// ============================================================================
__global__ void __launch_bounds__(256) gate_A(const float* __restrict__ u3p,
                                              const float* __restrict__ cu3p, int k) {
    __shared__ u64 tile[4096];
    __shared__ u64 sg[192];
    int tid = threadIdx.x, cta = blockIdx.x;
    u64* gp = (u64*)d_state + ((size_t)cta << 12);

    prep_A(sg, u3p, cu3p, k, tid);

    u64 v[16];
    const ulonglong2* g2 = (const ulonglong2*)gp;
#pragma unroll
    for (int j = 0; j < 8; j++) {  // v[r] = gp[(tid<<4)|r]
        ulonglong2 val = g2[tid * 8 + j];
        v[2 * j] = val.x; v[2 * j + 1] = val.y;
    }
    __syncthreads();

    A_body(v, tile, sg, tid);

    // coalesced store in w4 layout (canonical: tid | r<<8)
#pragma unroll
    for (int r = 0; r < 16; r++) gp[(r << 8) | tid] = v[r];
}

// ============================================================================
// Kernel B (k=1,2): direct w1 load. LAST fuses the pointwise finalize.
// ============================================================================
template <bool LAST>
__global__ void __launch_bounds__(256) gate_B(const float* __restrict__ u3p,
                                              const float* __restrict__ cu3p, int k,
                                              float* __restrict__ out) {
    __shared__ u64 tile[4096];
    __shared__ u64 sg[144];
    int tid = threadIdx.x, cta = blockIdx.x;

    if (tid < 9) prep_B(sg, u3p, cu3p, k, tid);

    u64* ds = (u64*)d_state;
    int b0 = (tid & 7) | (cta << 3) | ((tid >> 3) << 15);
    u64 v[16];
#pragma unroll
    for (int r = 0; r < 16; r++) v[r] = ds[b0 | (r << 11)];  // l3..6 = q11..14 = r
    __syncthreads();

    B_body<false>(v, tile, sg, tid);

    if (!LAST) {
        B_store(v, ds, tid, cta);
    } else {
        // fused finalize (R4, proven): exit layout g = r2.. ->
        // g = (tid&3)<<1 ... with q0 = h pair; out = brev20(g)
        float sum = 0.f;
#pragma unroll
        for (int h = 0; h < 2; h++) {
            float xv[8];
#pragma unroll
            for (int rr = 0; rr < 8; rr++) {
                float2 a = unp(v[rr | (h << 3)]);
                float pr = a.x * a.x + a.y * a.y;
                float t = 0.8f * tanh_ap(52428.8f * pr);  // gamma * 2^19
                float x = __powf(t, 0.3f);
                int j = ((rr & 1) << 2) | (rr & 2) | (rr >> 2);  // brev3
                xv[j] = x;
                sum += x;
            }
            int g0 = h | ((tid & 3) << 1) | (cta << 3) | ((tid >> 2) << 11);
            int obase = (int)(__brev((unsigned)g0) >> 12);  // low 3 bits zero
            float4* o4 = (float4*)(out + obase);
            o4[0] = make_float4(xv[0], xv[1], xv[2], xv[3]);
            o4[1] = make_float4(xv[4], xv[5], xv[6], xv[7]);
        }
        for (int o = 16; o > 0; o >>= 1) sum += __shfl_down_sync(0xffffffffu, sum, o);
        __shared__ float red[8];
        if ((tid & 31) == 0) red[tid >> 5] = sum;
        __syncthreads();
        if (tid == 0) {
            float s = 0.f;
#pragma unroll
            for (int w = 0; w < 8; w++) s += red[w];
            d_partial[cta] = s;
        }
    }
}

// mean from 256 partials (redundant per CTA, L2-hot), then subtract
__global__ void __launch_bounds__(256) finalize_sub(float4* __restrict__ o4) {
    int tid = threadIdx.x;
    int i = blockIdx.x * 256 + tid;
    float4 x = o4[i];

    float s = d_partial[tid];
    for (int o = 16; o > 0; o >>= 1) s += __shfl_down_sync(0xffffffffu, s, o);
    __shared__ float red[8];
    __shared__ float mean;
    if ((tid & 31) == 0) red[tid >> 5] = s;
    __syncthreads();
    if (tid == 0) {
        float t = 0.f;
#pragma unroll
        for (int w = 0; w < 8; w++) t += red[w];
        mean = t * (1.0f / 1048576.0f);
    }
    __syncthreads();
    float m = mean;
    x.x -= m; x.y -= m; x.z -= m; x.w -= m;
    o4[i] = x;
}

extern "C" void kernel_launch(void* const* d_in, const int* in_sizes, int n_in,
                              void* d_out, int out_size) {
    const float* u3p = (const float*)d_in[0];   // (3, 20, 3)
    const float* cu3p = (const float*)d_in[1];  // (3, 20, 3)
    float* out = (float*)d_out;                 // 2^20 floats

    gate_AB0<<<256, 256>>>(u3p, cu3p);
    gate_A<<<256, 256>>>(u3p, cu3p, 1);
    gate_B<false><<<256, 256>>>(u3p, cu3p, 1, out);
    gate_A<<<256, 256>>>(u3p, cu3p, 2);
    gate_B<true><<<256, 256>>>(u3p, cu3p, 2, out);
    finalize_sub<<<1024, 256>>>((float4*)out);
}